// round 1
// baseline (speedup 1.0000x reference)
#include <cuda_runtime.h>
#include <cstdint>

// Problem constants (from reference): N=100000, D=64, H=4, DK=16, E=1600000
#define MAXN 100000
#define MAXE 1600000

// xt = C1*x + C2*(x @ W^T)   where [[C1,C2],[-C2,C1-ish]] = M^4, M=[[1,.25],[-.25,1]]
#define C1 0.62890625f
#define C2 0.9375f
#define ALPHA 0.2f

// Scratch (static device arrays — no allocation allowed)
__device__ float  g_xt[MAXN * 64];    // 25.6 MB
__device__ float4 g_ssrc[MAXN];       // per-node per-head src score
__device__ float4 g_sdst[MAXN];       // per-node per-head dst score
__device__ float4 g_denom[MAXN];      // softmax denominators (per col node, per head)

__device__ __forceinline__ void red_add_v4(float* p, float a, float b, float c, float d) {
    asm volatile("red.global.add.v4.f32 [%0], {%1, %2, %3, %4};"
                 :: "l"(p), "f"(a), "f"(b), "f"(c), "f"(d) : "memory");
}

__device__ __forceinline__ float lrelu(float v) {
    return v > 0.0f ? v : ALPHA * v;
}

// ---------------------------------------------------------------------------
// Zero out + denom (out is poisoned by harness; denom must be zeroed per replay)
// ---------------------------------------------------------------------------
__global__ void kZero(float4* __restrict__ out4, int n4, int n_nodes) {
    int i = blockIdx.x * blockDim.x + threadIdx.x;
    float4 z = make_float4(0.f, 0.f, 0.f, 0.f);
    if (i < n4) out4[i] = z;
    if (i < n_nodes) g_denom[i] = z;
}

// ---------------------------------------------------------------------------
// Per-node: xt = C1*x + C2*(x@W^T); s_src[h] = xt[h]·a[:16]; s_dst[h] = xt[h]·a[16:]
// One thread per node. x row in registers, W in shared (broadcast reads).
// ---------------------------------------------------------------------------
__global__ void __launch_bounds__(256) kNode(
    const float* __restrict__ x, const float* __restrict__ W,
    const float* __restrict__ a, int n_nodes)
{
    __shared__ float4 sW[1024];   // 64x64 W, row-major, as float4
    __shared__ float  sA[32];
    for (int k = threadIdx.x; k < 1024; k += blockDim.x)
        sW[k] = ((const float4*)W)[k];
    if (threadIdx.x < 32) sA[threadIdx.x] = a[threadIdx.x];
    __syncthreads();

    int n = blockIdx.x * blockDim.x + threadIdx.x;
    if (n >= n_nodes) return;

    float4 xr[16];
    const float4* xv = (const float4*)(x + (size_t)n * 64);
#pragma unroll
    for (int i = 0; i < 16; i++) xr[i] = xv[i];

    float ss[4] = {0.f, 0.f, 0.f, 0.f};
    float sd[4] = {0.f, 0.f, 0.f, 0.f};
    float4* xtv = (float4*)(g_xt + (size_t)n * 64);

#pragma unroll
    for (int h = 0; h < 4; h++) {
#pragma unroll
        for (int kq = 0; kq < 4; kq++) {
            const int jq = h * 4 + kq;      // float4 group index (j = jq*4+m)
            float4 xq = xr[jq];
            float4 outq;
#pragma unroll
            for (int m = 0; m < 4; m++) {
                const int j = jq * 4 + m;   // output feature index
                const float4* wr = &sW[j * 16];
                float p = 0.f;
#pragma unroll
                for (int i = 0; i < 16; i++) {
                    float4 w  = wr[i];
                    float4 xx = xr[i];
                    p = fmaf(xx.x, w.x, p);
                    p = fmaf(xx.y, w.y, p);
                    p = fmaf(xx.z, w.z, p);
                    p = fmaf(xx.w, w.w, p);
                }
                float xc = (m == 0) ? xq.x : (m == 1) ? xq.y : (m == 2) ? xq.z : xq.w;
                float t  = fmaf(C2, p, C1 * xc);
                const int k = kq * 4 + m;   // index within head (0..15)
                ss[h] = fmaf(t, sA[k],      ss[h]);
                sd[h] = fmaf(t, sA[16 + k], sd[h]);
                if      (m == 0) outq.x = t;
                else if (m == 1) outq.y = t;
                else if (m == 2) outq.z = t;
                else             outq.w = t;
            }
            xtv[jq] = outq;
        }
    }
    g_ssrc[n] = make_float4(ss[0], ss[1], ss[2], ss[3]);
    g_sdst[n] = make_float4(sd[0], sd[1], sd[2], sd[3]);
}

// ---------------------------------------------------------------------------
// Edge pass 1: denom[col][h] += exp(leaky(s_src[row][h] + s_dst[col][h]))
// (softmax-shift dropped: scores bounded ~|17|, safe in fp32)
// ---------------------------------------------------------------------------
__global__ void __launch_bounds__(256) kDenom(const int* __restrict__ ei, int E) {
    int e = blockIdx.x * blockDim.x + threadIdx.x;
    if (e >= E) return;
    int r = __ldg(ei + e);
    int c = __ldg(ei + E + e);
    float4 s1 = g_ssrc[r];
    float4 s2 = g_sdst[c];
    float e0 = __expf(lrelu(s1.x + s2.x));
    float e1 = __expf(lrelu(s1.y + s2.y));
    float e2 = __expf(lrelu(s1.z + s2.z));
    float e3 = __expf(lrelu(s1.w + s2.w));
    red_add_v4((float*)&g_denom[c], e0, e1, e2, e3);
}

// ---------------------------------------------------------------------------
// Edge pass 2: w = mean_h( e_h / (denom[col][h]+1e-16) );  out[row] += w*xt[col]
// 16 lanes per edge: redundant scalar w-compute (broadcast loads), fully
// coalesced float4 gather of xt[col], vector red scatter into out[row].
// ---------------------------------------------------------------------------
__global__ void __launch_bounds__(256) kScatter(
    const int* __restrict__ ei, float* __restrict__ out, int E)
{
    int grp  = threadIdx.x >> 4;           // 16 groups / block
    int lane = threadIdx.x & 15;
    int e = blockIdx.x * 16 + grp;
    if (e >= E) return;

    int r = __ldg(ei + e);
    int c = __ldg(ei + E + e);
    float4 s1 = g_ssrc[r];
    float4 s2 = g_sdst[c];
    float4 d  = g_denom[c];

    float w0 = __fdividef(__expf(lrelu(s1.x + s2.x)), d.x + 1e-16f);
    float w1 = __fdividef(__expf(lrelu(s1.y + s2.y)), d.y + 1e-16f);
    float w2 = __fdividef(__expf(lrelu(s1.z + s2.z)), d.z + 1e-16f);
    float w3 = __fdividef(__expf(lrelu(s1.w + s2.w)), d.w + 1e-16f);
    float w = 0.25f * (w0 + w1 + w2 + w3);

    float4 xv = ((const float4*)(g_xt + (size_t)c * 64))[lane];
    red_add_v4(out + (size_t)r * 64 + lane * 4,
               w * xv.x, w * xv.y, w * xv.z, w * xv.w);
}

// ---------------------------------------------------------------------------
// inputs (metadata order): x[N*64] f32, edge_index[2*E] i32, edge_weight[E] f32
//                          (unused by reference), W[64*64] f32, a[32] f32
// output: out[N*64] f32
// ---------------------------------------------------------------------------
extern "C" void kernel_launch(void* const* d_in, const int* in_sizes, int n_in,
                              void* d_out, int out_size) {
    const float* x  = (const float*)d_in[0];
    const int*   ei = (const int*)d_in[1];
    const float* W  = (const float*)d_in[3];
    const float* a  = (const float*)d_in[4];
    float* out = (float*)d_out;

    int N = in_sizes[0] / 64;
    int E = in_sizes[2];
    int n4 = N * 16;   // float4 count of out

    kZero<<<(n4 + 255) / 256, 256>>>((float4*)out, n4, N);
    kNode<<<(N + 255) / 256, 256>>>(x, W, a, N);
    kDenom<<<(E + 255) / 256, 256>>>(ei, E);
    kScatter<<<(E + 15) / 16, 256>>>(ei, out, E);
}

// round 3
// speedup vs baseline: 1.0642x; 1.0642x over previous
#include <cuda_runtime.h>
#include <cstdint>

// Problem constants: N=100000, D=64, H=4, DK=16, E=1600000
#define MAXN 100000
#define MAXE 1600000

// xt = C1*x + C2*(x @ W^T)  where M^4, M=[[1,.25],[-.25,1]] (exact binary fracs)
#define C1 0.62890625f
#define C2 0.9375f
#define ALPHA 0.2f

// Scratch (static device arrays — no allocation allowed)
__device__ float  g_xt[MAXN * 64];    // transformed features (25.6 MB)
__device__ float4 g_ssrc[MAXN];       // per-node per-head src score
__device__ float4 g_sdst[MAXN];       // per-node per-head dst score
__device__ float4 g_denom[MAXN];      // softmax denom -> inverted in kScan
__device__ int    g_cnt[MAXN];        // out-degree by row
__device__ int    g_start[MAXN];      // CSR row start
__device__ int    g_cursor[MAXN];     // fill cursor
__device__ int    g_total;            // scan running offset
__device__ float2 g_cw[MAXE];         // per-edge (col, w)

__device__ __forceinline__ float lrelu(float v) {
    return v > 0.0f ? v : ALPHA * v;
}

// ---------------------------------------------------------------------------
// Zero per-replay state (denom, counts, scan total)
// ---------------------------------------------------------------------------
__global__ void kZero(int n_nodes) {
    int i = blockIdx.x * blockDim.x + threadIdx.x;
    if (i < n_nodes) {
        g_denom[i] = make_float4(0.f, 0.f, 0.f, 0.f);
        g_cnt[i] = 0;
    }
    if (i == 0) g_total = 0;
}

// ---------------------------------------------------------------------------
// Per-node: xt = C1*x + C2*(x@W^T); per-head scores vs a[:16], a[16:]
// One thread per node; W broadcast from shared; x row in registers.
// ---------------------------------------------------------------------------
__global__ void __launch_bounds__(256) kNode(
    const float* __restrict__ x, const float* __restrict__ W,
    const float* __restrict__ a, int n_nodes)
{
    __shared__ float4 sW[1024];   // 64x64 W row-major as float4
    __shared__ float  sA[32];
    for (int k = threadIdx.x; k < 1024; k += blockDim.x)
        sW[k] = ((const float4*)W)[k];
    if (threadIdx.x < 32) sA[threadIdx.x] = a[threadIdx.x];
    __syncthreads();

    int n = blockIdx.x * blockDim.x + threadIdx.x;
    if (n >= n_nodes) return;

    float4 xr[16];
    const float4* xv = (const float4*)(x + (size_t)n * 64);
#pragma unroll
    for (int i = 0; i < 16; i++) xr[i] = xv[i];

    float ss[4] = {0.f, 0.f, 0.f, 0.f};
    float sd[4] = {0.f, 0.f, 0.f, 0.f};
    float4* xtv = (float4*)(g_xt + (size_t)n * 64);

#pragma unroll
    for (int h = 0; h < 4; h++) {
#pragma unroll
        for (int kq = 0; kq < 4; kq++) {
            const int jq = h * 4 + kq;
            float4 xq = xr[jq];
            float4 outq;
#pragma unroll
            for (int m = 0; m < 4; m++) {
                const int j = jq * 4 + m;
                const float4* wr = &sW[j * 16];
                float p = 0.f;
#pragma unroll
                for (int i = 0; i < 16; i++) {
                    float4 w  = wr[i];
                    float4 xx = xr[i];
                    p = fmaf(xx.x, w.x, p);
                    p = fmaf(xx.y, w.y, p);
                    p = fmaf(xx.z, w.z, p);
                    p = fmaf(xx.w, w.w, p);
                }
                float xc = (m == 0) ? xq.x : (m == 1) ? xq.y : (m == 2) ? xq.z : xq.w;
                float t  = fmaf(C2, p, C1 * xc);
                const int k = kq * 4 + m;
                ss[h] = fmaf(t, sA[k],      ss[h]);
                sd[h] = fmaf(t, sA[16 + k], sd[h]);
                if      (m == 0) outq.x = t;
                else if (m == 1) outq.y = t;
                else if (m == 2) outq.z = t;
                else             outq.w = t;
            }
            xtv[jq] = outq;
        }
    }
    g_ssrc[n] = make_float4(ss[0], ss[1], ss[2], ss[3]);
    g_sdst[n] = make_float4(sd[0], sd[1], sd[2], sd[3]);
}

// ---------------------------------------------------------------------------
// Edge pass 1: denom[col][h] += exp(leaky(.)); count edges per row.
// (softmax-shift safely dropped: |score| <~ 17, exp within fp32 range)
// ---------------------------------------------------------------------------
__global__ void __launch_bounds__(256) kDenom(const int* __restrict__ ei, int E) {
    int e = blockIdx.x * blockDim.x + threadIdx.x;
    if (e >= E) return;
    int r = __ldg(ei + e);
    int c = __ldg(ei + E + e);
    float4 s1 = g_ssrc[r];
    float4 s2 = g_sdst[c];
    float e0 = __expf(lrelu(s1.x + s2.x));
    float e1 = __expf(lrelu(s1.y + s2.y));
    float e2 = __expf(lrelu(s1.z + s2.z));
    float e3 = __expf(lrelu(s1.w + s2.w));
    float* d = (float*)&g_denom[c];
    asm volatile("red.global.add.v4.f32 [%0], {%1, %2, %3, %4};"
                 :: "l"(d), "f"(e0), "f"(e1), "f"(e2), "f"(e3) : "memory");
    atomicAdd(&g_cnt[r], 1);
}

// ---------------------------------------------------------------------------
// Prefix scan of counts (chunk=1024/block, atomic block offset — order-free)
// Also inverts denominators in place: denom <- 1/(denom+1e-16).
// ---------------------------------------------------------------------------
__global__ void __launch_bounds__(1024) kScan(int n_nodes) {
    __shared__ int s[1024];
    __shared__ int base;
    int tid = threadIdx.x;
    int i = blockIdx.x * 1024 + tid;
    int v = (i < n_nodes) ? g_cnt[i] : 0;
    s[tid] = v;
    __syncthreads();
#pragma unroll
    for (int d = 1; d < 1024; d <<= 1) {
        int t = (tid >= d) ? s[tid - d] : 0;
        __syncthreads();
        s[tid] += t;
        __syncthreads();
    }
    if (tid == 1023) base = atomicAdd(&g_total, s[1023]);
    __syncthreads();
    if (i < n_nodes) {
        int start = base + s[tid] - v;   // exclusive within chunk + global base
        g_start[i] = start;
        g_cursor[i] = start;
        float4 dn = g_denom[i];
        g_denom[i] = make_float4(__frcp_rn(dn.x + 1e-16f), __frcp_rn(dn.y + 1e-16f),
                                 __frcp_rn(dn.z + 1e-16f), __frcp_rn(dn.w + 1e-16f));
    }
}

// ---------------------------------------------------------------------------
// Edge pass 2: compute per-edge weight once, fill CSR slot (col, w)
// ---------------------------------------------------------------------------
__global__ void __launch_bounds__(256) kFill(const int* __restrict__ ei, int E) {
    int e = blockIdx.x * blockDim.x + threadIdx.x;
    if (e >= E) return;
    int r = __ldg(ei + e);
    int c = __ldg(ei + E + e);
    float4 s1 = g_ssrc[r];
    float4 s2 = g_sdst[c];
    float4 di = g_denom[c];   // inverted
    float w = 0.25f * (__expf(lrelu(s1.x + s2.x)) * di.x +
                       __expf(lrelu(s1.y + s2.y)) * di.y +
                       __expf(lrelu(s1.z + s2.z)) * di.z +
                       __expf(lrelu(s1.w + s2.w)) * di.w);
    int pos = atomicAdd(&g_cursor[r], 1);
    g_cw[pos] = make_float2(__int_as_float(c), w);
}

// ---------------------------------------------------------------------------
// Pull: one warp per row. Lane l owns floats [2l, 2l+1] of the feature dim.
// cw prefetched one iteration ahead to keep the xt gather off the chain.
// ---------------------------------------------------------------------------
__global__ void __launch_bounds__(256) kPull(float* __restrict__ out, int n_nodes) {
    int row = blockIdx.x * (blockDim.x >> 5) + (threadIdx.x >> 5);
    if (row >= n_nodes) return;
    int lane = threadIdx.x & 31;
    int start = g_start[row];
    int cnt   = g_cnt[row];

    const float2* __restrict__ xt2 = (const float2*)g_xt;
    float ax = 0.f, ay = 0.f;
    float2 cw = (cnt > 0) ? __ldg(&g_cw[start]) : make_float2(0.f, 0.f);
    for (int j = 0; j < cnt; j++) {
        float2 nxt = (j + 1 < cnt) ? __ldg(&g_cw[start + j + 1]) : cw;
        int c = __float_as_int(cw.x);
        float2 xv = __ldg(&xt2[(size_t)c * 32 + lane]);
        ax = fmaf(cw.y, xv.x, ax);
        ay = fmaf(cw.y, xv.y, ay);
        cw = nxt;
    }
    ((float2*)out)[(size_t)row * 32 + lane] = make_float2(ax, ay);
}

// ---------------------------------------------------------------------------
// inputs: x[N*64] f32, edge_index[2*E] i32, edge_weight[E] f32 (unused),
//         W[64*64] f32, a[32] f32   |  output: out[N*64] f32
// ---------------------------------------------------------------------------
extern "C" void kernel_launch(void* const* d_in, const int* in_sizes, int n_in,
                              void* d_out, int out_size) {
    const float* x  = (const float*)d_in[0];
    const int*   ei = (const int*)d_in[1];
    const float* W  = (const float*)d_in[3];
    const float* a  = (const float*)d_in[4];
    float* out = (float*)d_out;

    int N = in_sizes[0] / 64;
    int E = in_sizes[2];

    kZero<<<(N + 255) / 256, 256>>>(N);
    kNode<<<(N + 255) / 256, 256>>>(x, W, a, N);
    kDenom<<<(E + 255) / 256, 256>>>(ei, E);
    kScan<<<(N + 1023) / 1024, 1024>>>(N);
    kFill<<<(E + 255) / 256, 256>>>(ei, E);
    kPull<<<(N + 7) / 8, 256>>>(out, N);
}